// round 15
// baseline (speedup 1.0000x reference)
#include <cuda_runtime.h>
#include <cuda_bf16.h>
#include <math.h>
#include <stdint.h>

#define NB 16
#define NT 2048
#define ND 256
#define NC 128
#define MAXK 20
#define WLEN 19      // live window elements
#define CHROWS 64    // emission chunk rows
#define NCHUNK (NT / CHROWS)   // 32
#define NRB 8        // rec blocks (2 batches each)

typedef unsigned long long ull;

union U2 { float4 f4; ull u[2]; };

#define FMA2(acc, a, b) asm("fma.rn.f32x2 %0, %1, %2, %0;" : "+l"(acc) : "l"(a), "l"(b))
#define MUL2(d, a, b)   asm("mul.rn.f32x2 %0, %1, %2;" : "=l"(d) : "l"(a), "l"(b))
#define PACK2(d, x, y)  asm("mov.b64 %0, {%1, %2};" : "=l"(d) : "f"(x), "f"(y))
#define UNPACK2(x, y, d) asm("mov.b64 {%0, %1}, %2;" : "=f"(x), "=f"(y) : "l"(d))
#define HFMA2BF(acc, a, b) asm("fma.rn.bf16x2 %0, %1, %2, %0;" : "+r"(acc) : "r"(a), "r"(b))

// ---------- device scratch ----------
__device__ float g_E[NC * NC];
__device__ float g_winit[NC];
__device__ float g_dtab[MAXK * NC];
__device__ float g_miT[ND * NC];
__device__ float g_cb[NC];
__device__ float g_iv[ND];
__device__ float g_f[(size_t)NB * NT * NC];
__device__ float g_mu[NB * NT];
__device__ int   g_done[NB * NCHUNK];

// ---------- prep_misc: 1 block x 256 ----------
__global__ void prep_misc(const float* __restrict__ means,
                          const float* __restrict__ cov,
                          const float* __restrict__ initlg,
                          const float* __restrict__ lograte) {
    const int t = threadIdx.x;
    const int lane = t & 31, w = t >> 5;
    __shared__ float red[8];
    __shared__ float s_cst;
    __shared__ float s_iv[ND];

    g_done[t] = 0;
    g_done[t + 256] = 0;

    float cv = cov[t];
    float iv = __fdividef(1.0f, cv);
    g_iv[t] = iv;
    s_iv[t] = iv;
    float ls = __logf(cv);
#pragma unroll
    for (int o = 16; o >= 1; o >>= 1)
        ls += __shfl_xor_sync(0xffffffffu, ls, o);
    if (lane == 0) red[w] = ls;
    __syncthreads();
    if (t == 0) {
        float tot = 0.f;
        for (int i = 0; i < 8; ++i) tot += red[i];
        s_cst = -0.5f * (256.0f * 1.8378770664093453f + tot);
    }
    __syncthreads();
    const float cst = s_cst;

    for (int ci = 0; ci < 16; ++ci) {
        int c = ci * 8 + w;
        float p = 0.f;
#pragma unroll
        for (int k = 0; k < 8; ++k) {
            int d = k * 32 + lane;
            float m = means[c * ND + d];
            p = fmaf(m * m, s_iv[d], p);
        }
#pragma unroll
        for (int o = 16; o >= 1; o >>= 1)
            p += __shfl_xor_sync(0xffffffffu, p, o);
        if (lane == 0) g_cb[c] = cst - 0.5f * p;
    }

    if (t < NC) {
        float il = initlg[t];
        float mx = il;
#pragma unroll
        for (int o = 16; o >= 1; o >>= 1)
            mx = fmaxf(mx, __shfl_xor_sync(0xffffffffu, mx, o));
        if (lane == 0) red[w] = mx;
    }
    __syncthreads();
    if (t < NC) {
        float mx = fmaxf(fmaxf(red[0], red[1]), fmaxf(red[2], red[3]));
        float il = initlg[t];
        float ex = __expf(il - mx);
        float s = ex;
#pragma unroll
        for (int o = 16; o >= 1; o >>= 1)
            s += __shfl_xor_sync(0xffffffffu, s, o);
        if (lane == 0) red[4 + w] = s;
        __syncthreads();
        float tot = (red[4] + red[5]) + (red[6] + red[7]);
        g_winit[t] = __fdividef(ex, tot);

        float r = lograte[t];
        float lam = __expf(r);
        float lg = 0.f;
        for (int l = 1; l <= MAXK; ++l) {
            lg += __logf((float)l);
            g_dtab[(l - 1) * NC + t] = __expf(fmaf((float)l, r, -lam) - lg);
        }
    }
}

// ---------- prep_trans: 1 block x 1024 ----------
__global__ __launch_bounds__(1024) void prep_trans(const float* __restrict__ trans) {
    const int t = threadIdx.x;
    const int j = t & 127;
    const int g = t >> 7;
    __shared__ float gmax[8][NC];
    __shared__ float gsum[8][NC];
    __shared__ float colmax[NC], colinv[NC];

    float v[16];
    float mx = -3.0e38f;
#pragma unroll
    for (int k = 0; k < 16; ++k) {
        int i = g * 16 + k;
        float x = trans[i * NC + j];
        if (i == j) x = -1.0e9f;
        v[k] = x;
        mx = fmaxf(mx, x);
    }
    gmax[g][j] = mx;
    __syncthreads();
    if (t < NC) {
        float m = gmax[0][t];
#pragma unroll
        for (int i = 1; i < 8; ++i) m = fmaxf(m, gmax[i][t]);
        colmax[t] = m;
    }
    __syncthreads();
    float cm = colmax[j];
    float ex[16], s = 0.f;
#pragma unroll
    for (int k = 0; k < 16; ++k) {
        ex[k] = __expf(v[k] - cm);
        s += ex[k];
    }
    gsum[g][j] = s;
    __syncthreads();
    if (t < NC) {
        float ss = 0.f;
#pragma unroll
        for (int i = 0; i < 8; ++i) ss += gsum[i][t];
        colinv[t] = __fdividef(1.0f, ss);
    }
    __syncthreads();
    float inv = colinv[j];
#pragma unroll
    for (int k = 0; k < 16; ++k) {
        int i = g * 16 + k;
        g_E[i * NC + j] = (i == j) ? 0.0f : ex[k] * inv;
    }
}

// ---------- prep_miT: 32 blocks x 256 ----------
__global__ void prep_miT(const float* __restrict__ means,
                         const float* __restrict__ cov) {
    __shared__ float tile[32][33];
    const int t = threadIdx.x;
    const int tc = blockIdx.x & 3, td = blockIdx.x >> 2;
    const int c0 = tc * 32, d0 = td * 32;
    const int r = t >> 5, dl = t & 31;

    float iv = __fdividef(1.0f, cov[d0 + dl]);
#pragma unroll
    for (int k = 0; k < 4; ++k) {
        int rr = r + 8 * k;
        tile[rr][dl] = means[(c0 + rr) * ND + d0 + dl] * iv;
    }
    __syncthreads();
#pragma unroll
    for (int k = 0; k < 4; ++k) {
        int dr = r + 8 * k;
        g_miT[(d0 + dr) * NC + c0 + dl] = tile[dl][dr];
    }
}

// ---------- fused kernel: 8 rec blocks (2 batches each) + 512 producers ----------
__global__ __launch_bounds__(256) void fused_kernel(const float* __restrict__ feat,
                                                    const int* __restrict__ lengths,
                                                    float* __restrict__ out) {
    if (blockIdx.x >= NRB) {
        // ================= emission producer: 64 rows =================
        const int eb = blockIdx.x - NRB;
        const int chunk = eb >> 4;
        const int b = eb & 15;
        const int r0 = b * NT + chunk * CHROWS;

        __shared__ float A[CHROWS][40];
        __shared__ float Bt[32][132];
        __shared__ float ivs[32];

        const int tid = threadIdx.x;
        const int cg = tid & 15;
        const int rr = tid >> 4;

        ull acc2[4][4];
#pragma unroll
        for (int i = 0; i < 4; ++i)
#pragma unroll
            for (int k = 0; k < 4; ++k) acc2[i][k] = 0ull;
        float xq[4] = {0.f, 0.f, 0.f, 0.f};

        for (int d0 = 0; d0 < ND; d0 += 32) {
            __syncthreads();
#pragma unroll
            for (int k = 0; k < 2; ++k) {
                int i = tid + k * 256;
                int row = i >> 3, q = i & 7;
                *(float4*)&A[row][q * 4] =
                    *(const float4*)&feat[(size_t)(r0 + row) * ND + d0 + q * 4];
            }
#pragma unroll
            for (int k = 0; k < 4; ++k) {
                int i = tid + k * 256;
                int drow = i >> 5, q = i & 31;
                *(float4*)&Bt[drow][q * 4] =
                    *(const float4*)&g_miT[(size_t)(d0 + drow) * NC + q * 4];
            }
            if (tid < 32) ivs[tid] = g_iv[d0 + tid];
            __syncthreads();

#pragma unroll
            for (int u = 0; u < 2; ++u) {
                int dd = cg + u * 16;
                float iv = ivs[dd];
#pragma unroll
                for (int i = 0; i < 4; ++i) {
                    float a = A[rr + 16 * i][dd];
                    xq[i] = fmaf(a * iv, a, xq[i]);
                }
            }

#pragma unroll 8
            for (int dd = 0; dd < 32; ++dd) {
                U2 b0, b1;
                b0.f4 = *(const float4*)&Bt[dd][cg * 4];
                b1.f4 = *(const float4*)&Bt[dd][64 + cg * 4];
#pragma unroll
                for (int i = 0; i < 4; ++i) {
                    float a = A[rr + 16 * i][dd];
                    ull aa;
                    PACK2(aa, a, a);
                    FMA2(acc2[i][0], aa, b0.u[0]);
                    FMA2(acc2[i][1], aa, b0.u[1]);
                    FMA2(acc2[i][2], aa, b1.u[0]);
                    FMA2(acc2[i][3], aa, b1.u[1]);
                }
            }
        }

#pragma unroll
        for (int o = 1; o < 16; o <<= 1) {
#pragma unroll
            for (int i = 0; i < 4; ++i)
                xq[i] += __shfl_xor_sync(0xffffffffu, xq[i], o, 16);
        }

        float cb[8];
        {
            float4 cb0 = *(const float4*)&g_cb[cg * 4];
            float4 cb1 = *(const float4*)&g_cb[64 + cg * 4];
            cb[0] = cb0.x; cb[1] = cb0.y; cb[2] = cb0.z; cb[3] = cb0.w;
            cb[4] = cb1.x; cb[5] = cb1.y; cb[6] = cb1.z; cb[7] = cb1.w;
        }
        const float L2E = 1.4426950408889634f;

#pragma unroll
        for (int i = 0; i < 4; ++i) {
            float hq = -0.5f * xq[i];
            float e[8], m = -3.0e38f;
#pragma unroll
            for (int k = 0; k < 4; ++k) {
                float lo, hi;
                UNPACK2(lo, hi, acc2[i][k]);
                e[k * 2] = lo + hq + cb[k * 2];
                e[k * 2 + 1] = hi + hq + cb[k * 2 + 1];
            }
#pragma unroll
            for (int k = 0; k < 8; ++k) m = fmaxf(m, e[k]);
#pragma unroll
            for (int off = 8; off >= 1; off >>= 1)
                m = fmaxf(m, __shfl_xor_sync(0xffffffffu, m, off, 16));
            float4 o0, o1;
            o0.x = exp2f((e[0] - m) * L2E); o0.y = exp2f((e[1] - m) * L2E);
            o0.z = exp2f((e[2] - m) * L2E); o0.w = exp2f((e[3] - m) * L2E);
            o1.x = exp2f((e[4] - m) * L2E); o1.y = exp2f((e[5] - m) * L2E);
            o1.z = exp2f((e[6] - m) * L2E); o1.w = exp2f((e[7] - m) * L2E);
            size_t row = (size_t)(r0 + rr + 16 * i);
            *(float4*)&g_f[row * NC + cg * 4] = o0;
            *(float4*)&g_f[row * NC + 64 + cg * 4] = o1;
            if (cg == 0) g_mu[row] = m;
        }

        __threadfence();
        __syncthreads();
        if (tid == 0) atomicExch(&g_done[b * NCHUNK + chunk], 1);
        return;
    }

    // ============ recursion: 2 batches interleaved in 4 warps ============
    if (threadIdx.x >= 128) return;

    const int b0 = blockIdx.x * 2, b1 = b0 + 1;
    const int c = threadIdx.x;
    const int w = c >> 5, lane = c & 31;
    __shared__ __align__(16) unsigned short psbA[2][NC];
    __shared__ __align__(16) unsigned short psbB[2][NC];
    __shared__ float shsA[4], shsB[4];

    // shared E row as bf16x2 (adjacent channels)
    unsigned Eb[64];
#pragma unroll
    for (int k = 0; k < 64; ++k) {
        __nv_bfloat162 t2 = __floats2bfloat162_rn(g_E[c * NC + 2 * k],
                                                  g_E[c * NC + 2 * k + 1]);
        Eb[k] = *(unsigned*)&t2;
    }
    const float Dr0 = g_dtab[c];
    ull Dr2[WLEN];     // Dr2[i] = pack(D[i+1], D[i+1])
#pragma unroll
    for (int j = 0; j < WLEN; ++j) {
        float d = g_dtab[(j + 1) * NC + c];
        PACK2(Dr2[j], d, d);
    }
    ull v2[WLEN];      // packed window: lo = batch A, hi = batch B
#pragma unroll
    for (int j = 0; j < WLEN; ++j) v2[j] = 0ull;

    const int lenA = lengths[b0], lenB = lengths[b1];
    const int tmax = lenA > lenB ? lenA : lenB;
    const float* fpA = g_f + (size_t)b0 * NT * NC;
    const float* fpB = g_f + (size_t)b1 * NT * NC;
    const float* mupA = g_mu + b0 * NT;
    const float* mupB = g_mu + b1 * NT;

    int qreadyA = -1, qreadyB = -1;
#define WAIT_CHUNK(bb, q, qr)                                                \
    if ((q) > (qr)) {                                                        \
        const int* fl = &g_done[(bb) * NCHUNK + (q)];                        \
        int d_;                                                              \
        do {                                                                 \
            asm volatile("ld.global.cg.b32 %0, [%1];" : "=r"(d_) : "l"(fl) : "memory"); \
            if (!d_) __nanosleep(64);                                        \
        } while (!d_);                                                       \
        (qr) = (q);                                                          \
        __threadfence();                                                     \
    }

    WAIT_CHUNK(b0, 0, qreadyA);
    WAIT_CHUNK(b1, 0, qreadyB);

    float wvA = g_winit[c], wvB = wvA;
    float frA = __ldg(&fpA[c]);
    float frB = __ldg(&fpB[c]);
    float alA = frA * (wvA * Dr0);
    float alB = frB * (wvB * Dr0);
    float sigmaA = __ldg(&mupA[0]), sigmaB = __ldg(&mupB[0]);
    int ksA = 0, ksB = 0, kcurA = 0, kcurB = 0;
    float rmA = 1.0f, rmB = 1.0f;
    float pA1 = __ldg(&fpA[NC + c]),     mA1 = __ldg(&mupA[1]);
    float pA2 = __ldg(&fpA[2 * NC + c]), mA2 = __ldg(&mupA[2]);
    float pB1 = __ldg(&fpB[NC + c]),     mB1 = __ldg(&mupB[1]);
    float pB2 = __ldg(&fpB[2 * NC + c]), mB2 = __ldg(&mupB[2]);

    for (int t = 1;; ++t) {
        const int par = t & 1;
        const bool endA = (t == lenA), endB = (t == lenB);

        if (endA) {
            float s = alA;
#pragma unroll
            for (int o = 16; o >= 1; o >>= 1)
                s += __shfl_xor_sync(0xffffffffu, s, o);
            if (lane == 0) shsA[w] = s;
        }
        if (endB) {
            float s = alB;
#pragma unroll
            for (int o = 16; o >= 1; o >>= 1)
                s += __shfl_xor_sync(0xffffffffu, s, o);
            if (lane == 0) shsB[w] = s;
        }

        // publish both alphas (bf16), one barrier
        {
            __nv_bfloat16 aa = __float2bfloat16(alA);
            __nv_bfloat16 ab = __float2bfloat16(alB);
            psbA[par][c] = *(unsigned short*)&aa;
            psbB[par][c] = *(unsigned short*)&ab;
        }
        __syncthreads();

        if (endA && c == 0) {
            float st = (shsA[0] + shsA[1]) + (shsA[2] + shsA[3]);
            out[b0] = sigmaA + (float)ksA * 0.6931471805599453f + logf(st);
        }
        if (endB && c == 0) {
            float st = (shsB[0] + shsB[1]) + (shsB[2] + shsB[3]);
            out[b1] = sigmaB + (float)ksB * 0.6931471805599453f + logf(st);
        }
        if (t == tmax) break;

        // prefetch row t+2 for both batches
        int tn = (t + 2 < NT) ? t + 2 : (NT - 1);
        int qn = tn >> 6;
        WAIT_CHUNK(b0, qn, qreadyA);
        float fNA = __ldg(&fpA[(size_t)tn * NC + c]);
        float mNA = __ldg(&mupA[tn]);
        WAIT_CHUNK(b1, qn, qreadyB);
        float fNB = __ldg(&fpB[(size_t)tn * NC + c]);
        float mNB = __ldg(&mupB[tn]);

        // block maxes (exponent only), matvec shadow
        {
            uint2 q2 = ((const uint2*)&psbA[par][0])[lane];
            unsigned u0 = q2.x << 16, u1 = q2.x & 0xffff0000u;
            unsigned u2v = q2.y << 16, u3 = q2.y & 0xffff0000u;
            unsigned m01 = u0 > u1 ? u0 : u1;
            unsigned m23 = u2v > u3 ? u2v : u3;
            unsigned qm = m01 > m23 ? m01 : m23;
            unsigned mm;
            asm("redux.sync.max.u32 %0, %1, 0xffffffff;" : "=r"(mm) : "r"(qm));
            unsigned e = mm >> 23;
            rmA = __uint_as_float((254u - e) << 23);
            kcurA = (int)e - 127;
        }
        {
            uint2 q2 = ((const uint2*)&psbB[par][0])[lane];
            unsigned u0 = q2.x << 16, u1 = q2.x & 0xffff0000u;
            unsigned u2v = q2.y << 16, u3 = q2.y & 0xffff0000u;
            unsigned m01 = u0 > u1 ? u0 : u1;
            unsigned m23 = u2v > u3 ? u2v : u3;
            unsigned qm = m01 > m23 ? m01 : m23;
            unsigned mm;
            asm("redux.sync.max.u32 %0, %1, 0xffffffff;" : "=r"(mm) : "r"(qm));
            unsigned e = mm >> 23;
            rmB = __uint_as_float((254u - e) << 23);
            kcurB = (int)e - 127;
        }

        // packed window update with current fr (lanes: lo=A, hi=B)
        ull fr2, wv2;
        PACK2(fr2, frA, frB);
        PACK2(wv2, wvA, wvB);
#pragma unroll
        for (int j = WLEN - 1; j >= 1; --j) MUL2(v2[j], v2[j - 1], fr2);
        MUL2(v2[0], wv2, fr2);

        // packed duration dot for NEXT alphas
        ull d0 = 0ull, d1 = 0ull, d2 = 0ull, d3 = 0ull;
#pragma unroll
        for (int j = 0; j < WLEN; j += 4) {
            FMA2(d0, v2[j], Dr2[j]);
            if (j + 1 < WLEN) FMA2(d1, v2[j + 1], Dr2[j + 1]);
            if (j + 2 < WLEN) FMA2(d2, v2[j + 2], Dr2[j + 2]);
            if (j + 3 < WLEN) FMA2(d3, v2[j + 3], Dr2[j + 3]);
        }
        float dA0, dB0, dA1, dB1, dA2, dB2, dA3, dB3;
        UNPACK2(dA0, dB0, d0); UNPACK2(dA1, dB1, d1);
        UNPACK2(dA2, dB2, d2); UNPACK2(dA3, dB3, d3);
        float dsumA = (dA0 + dA1) + (dA2 + dA3);
        float dsumB = (dB0 + dB1) + (dB2 + dB3);

        // matvec A (bf16)
        {
            const uint4* pb4 = (const uint4*)&psbA[par][0];
            unsigned a0 = 0u, a1 = 0u, a2 = 0u, a3 = 0u;
#pragma unroll
            for (int kk = 0; kk < 16; ++kk) {
                uint4 q = pb4[kk];
                HFMA2BF(a0, Eb[4 * kk + 0], q.x);
                HFMA2BF(a1, Eb[4 * kk + 1], q.y);
                HFMA2BF(a2, Eb[4 * kk + 2], q.z);
                HFMA2BF(a3, Eb[4 * kk + 3], q.w);
            }
            float f0 = __uint_as_float(a0 << 16) + __uint_as_float(a0 & 0xffff0000u);
            float f1 = __uint_as_float(a1 << 16) + __uint_as_float(a1 & 0xffff0000u);
            float f2 = __uint_as_float(a2 << 16) + __uint_as_float(a2 & 0xffff0000u);
            float f3 = __uint_as_float(a3 << 16) + __uint_as_float(a3 & 0xffff0000u);
            wvA = (f0 + f1) + (f2 + f3);
        }
        // matvec B (bf16)
        {
            const uint4* pb4 = (const uint4*)&psbB[par][0];
            unsigned a0 = 0u, a1 = 0u, a2 = 0u, a3 = 0u;
#pragma unroll
            for (int kk = 0; kk < 16; ++kk) {
                uint4 q = pb4[kk];
                HFMA2BF(a0, Eb[4 * kk + 0], q.x);
                HFMA2BF(a1, Eb[4 * kk + 1], q.y);
                HFMA2BF(a2, Eb[4 * kk + 2], q.z);
                HFMA2BF(a3, Eb[4 * kk + 3], q.w);
            }
            float f0 = __uint_as_float(a0 << 16) + __uint_as_float(a0 & 0xffff0000u);
            float f1 = __uint_as_float(a1 << 16) + __uint_as_float(a1 & 0xffff0000u);
            float f2 = __uint_as_float(a2 << 16) + __uint_as_float(a2 & 0xffff0000u);
            float f3 = __uint_as_float(a3 << 16) + __uint_as_float(a3 & 0xffff0000u);
            wvB = (f0 + f1) + (f2 + f3);
        }

        // next alphas: short tails
        frA = pA1 * rmA;
        alA = frA * fmaf(wvA, Dr0, dsumA);
        sigmaA += mA1;
        ksA += kcurA;
        frB = pB1 * rmB;
        alB = frB * fmaf(wvB, Dr0, dsumB);
        sigmaB += mB1;
        ksB += kcurB;

        pA1 = pA2; mA1 = mA2; pA2 = fNA; mA2 = mNA;
        pB1 = pB2; mB1 = mB2; pB2 = fNB; mB2 = mNB;
    }
#undef WAIT_CHUNK
}

extern "C" void kernel_launch(void* const* d_in, const int* in_sizes, int n_in,
                              void* d_out, int out_size) {
    const float* feat    = (const float*)d_in[0];
    const int*   lengths = (const int*)d_in[1];
    const float* means   = (const float*)d_in[2];
    const float* cov     = (const float*)d_in[3];
    const float* trans   = (const float*)d_in[4];
    const float* initlg  = (const float*)d_in[5];
    const float* lograte = (const float*)d_in[6];
    float* out = (float*)d_out;

    prep_misc<<<1, 256>>>(means, cov, initlg, lograte);
    prep_trans<<<1, 1024>>>(trans);
    prep_miT<<<32, 256>>>(means, cov);
    fused_kernel<<<NRB + NB * NCHUNK, 256>>>(feat, lengths, out);
}

// round 16
// speedup vs baseline: 1.6908x; 1.6908x over previous
#include <cuda_runtime.h>
#include <cuda_bf16.h>
#include <math.h>
#include <stdint.h>

#define NB 16
#define NT 2048
#define ND 256
#define NC 128
#define MAXK 20
#define CHROWS 64
#define NCHUNK (NT / CHROWS)   // 32

typedef unsigned long long ull;

union U2 { float4 f4; ull u[2]; };

#define FMA2(acc, a, b) asm("fma.rn.f32x2 %0, %1, %2, %0;" : "+l"(acc) : "l"(a), "l"(b))
#define PACK2(d, x, y)  asm("mov.b64 %0, {%1, %2};" : "=l"(d) : "f"(x), "f"(y))
#define UNPACK2(x, y, d) asm("mov.b64 {%0, %1}, %2;" : "=f"(x), "=f"(y) : "l"(d))
#define HFMA2BF(acc, a, b) asm("fma.rn.bf16x2 %0, %1, %2, %0;" : "+r"(acc) : "r"(a), "r"(b))
#define HMUL2BF(d, a, b)   asm("mul.rn.bf16x2 %0, %1, %2;" : "=r"(d) : "r"(a), "r"(b))

// ---------- device scratch ----------
__device__ float g_E[NC * NC];
__device__ float g_winit[NC];
__device__ float g_dtab[MAXK * NC];
__device__ float g_miT[ND * NC];
__device__ float g_cb[NC];
__device__ float g_iv[ND];
__device__ float g_f[(size_t)NB * NT * NC];
__device__ float g_mu[NB * NT];
__device__ int   g_done[NB * NCHUNK];

// ---------- prep_misc: 1 block x 256 ----------
__global__ void prep_misc(const float* __restrict__ means,
                          const float* __restrict__ cov,
                          const float* __restrict__ initlg,
                          const float* __restrict__ lograte) {
    const int t = threadIdx.x;
    const int lane = t & 31, w = t >> 5;
    __shared__ float red[8];
    __shared__ float s_cst;
    __shared__ float s_iv[ND];

    g_done[t] = 0;
    g_done[t + 256] = 0;

    float cv = cov[t];
    float iv = __fdividef(1.0f, cv);
    g_iv[t] = iv;
    s_iv[t] = iv;
    float ls = __logf(cv);
#pragma unroll
    for (int o = 16; o >= 1; o >>= 1)
        ls += __shfl_xor_sync(0xffffffffu, ls, o);
    if (lane == 0) red[w] = ls;
    __syncthreads();
    if (t == 0) {
        float tot = 0.f;
        for (int i = 0; i < 8; ++i) tot += red[i];
        s_cst = -0.5f * (256.0f * 1.8378770664093453f + tot);
    }
    __syncthreads();
    const float cst = s_cst;

    for (int ci = 0; ci < 16; ++ci) {
        int c = ci * 8 + w;
        float p = 0.f;
#pragma unroll
        for (int k = 0; k < 8; ++k) {
            int d = k * 32 + lane;
            float m = means[c * ND + d];
            p = fmaf(m * m, s_iv[d], p);
        }
#pragma unroll
        for (int o = 16; o >= 1; o >>= 1)
            p += __shfl_xor_sync(0xffffffffu, p, o);
        if (lane == 0) g_cb[c] = cst - 0.5f * p;
    }

    if (t < NC) {
        float il = initlg[t];
        float mx = il;
#pragma unroll
        for (int o = 16; o >= 1; o >>= 1)
            mx = fmaxf(mx, __shfl_xor_sync(0xffffffffu, mx, o));
        if (lane == 0) red[w] = mx;
    }
    __syncthreads();
    if (t < NC) {
        float mx = fmaxf(fmaxf(red[0], red[1]), fmaxf(red[2], red[3]));
        float il = initlg[t];
        float ex = __expf(il - mx);
        float s = ex;
#pragma unroll
        for (int o = 16; o >= 1; o >>= 1)
            s += __shfl_xor_sync(0xffffffffu, s, o);
        if (lane == 0) red[4 + w] = s;
        __syncthreads();
        float tot = (red[4] + red[5]) + (red[6] + red[7]);
        g_winit[t] = __fdividef(ex, tot);

        float r = lograte[t];
        float lam = __expf(r);
        float lg = 0.f;
        for (int l = 1; l <= MAXK; ++l) {
            lg += __logf((float)l);
            g_dtab[(l - 1) * NC + t] = __expf(fmaf((float)l, r, -lam) - lg);
        }
    }
}

// ---------- prep_trans: 1 block x 1024 ----------
__global__ __launch_bounds__(1024) void prep_trans(const float* __restrict__ trans) {
    const int t = threadIdx.x;
    const int j = t & 127;
    const int g = t >> 7;
    __shared__ float gmax[8][NC];
    __shared__ float gsum[8][NC];
    __shared__ float colmax[NC], colinv[NC];

    float v[16];
    float mx = -3.0e38f;
#pragma unroll
    for (int k = 0; k < 16; ++k) {
        int i = g * 16 + k;
        float x = trans[i * NC + j];
        if (i == j) x = -1.0e9f;
        v[k] = x;
        mx = fmaxf(mx, x);
    }
    gmax[g][j] = mx;
    __syncthreads();
    if (t < NC) {
        float m = gmax[0][t];
#pragma unroll
        for (int i = 1; i < 8; ++i) m = fmaxf(m, gmax[i][t]);
        colmax[t] = m;
    }
    __syncthreads();
    float cm = colmax[j];
    float ex[16], s = 0.f;
#pragma unroll
    for (int k = 0; k < 16; ++k) {
        ex[k] = __expf(v[k] - cm);
        s += ex[k];
    }
    gsum[g][j] = s;
    __syncthreads();
    if (t < NC) {
        float ss = 0.f;
#pragma unroll
        for (int i = 0; i < 8; ++i) ss += gsum[i][t];
        colinv[t] = __fdividef(1.0f, ss);
    }
    __syncthreads();
    float inv = colinv[j];
#pragma unroll
    for (int k = 0; k < 16; ++k) {
        int i = g * 16 + k;
        g_E[i * NC + j] = (i == j) ? 0.0f : ex[k] * inv;
    }
}

// ---------- prep_miT: 32 blocks x 256 ----------
__global__ void prep_miT(const float* __restrict__ means,
                         const float* __restrict__ cov) {
    __shared__ float tile[32][33];
    const int t = threadIdx.x;
    const int tc = blockIdx.x & 3, td = blockIdx.x >> 2;
    const int c0 = tc * 32, d0 = td * 32;
    const int r = t >> 5, dl = t & 31;

    float iv = __fdividef(1.0f, cov[d0 + dl]);
#pragma unroll
    for (int k = 0; k < 4; ++k) {
        int rr = r + 8 * k;
        tile[rr][dl] = means[(c0 + rr) * ND + d0 + dl] * iv;
    }
    __syncthreads();
#pragma unroll
    for (int k = 0; k < 4; ++k) {
        int dr = r + 8 * k;
        g_miT[(d0 + dr) * NC + c0 + dl] = tile[dl][dr];
    }
}

// ---------- fused kernel: 16 rec blocks + 512 emission producers ----------
__global__ __launch_bounds__(256) void fused_kernel(const float* __restrict__ feat,
                                                    const int* __restrict__ lengths,
                                                    float* __restrict__ out) {
    if (blockIdx.x >= NB) {
        // ================= emission producer: 64 rows =================
        const int eb = blockIdx.x - NB;
        const int chunk = eb >> 4;
        const int b = eb & 15;
        const int r0 = b * NT + chunk * CHROWS;

        __shared__ float A[CHROWS][40];
        __shared__ float Bt[32][132];
        __shared__ float ivs[32];

        const int tid = threadIdx.x;
        const int cg = tid & 15;
        const int rr = tid >> 4;

        ull acc2[4][4];
#pragma unroll
        for (int i = 0; i < 4; ++i)
#pragma unroll
            for (int k = 0; k < 4; ++k) acc2[i][k] = 0ull;
        float xq[4] = {0.f, 0.f, 0.f, 0.f};

        for (int d0 = 0; d0 < ND; d0 += 32) {
            __syncthreads();
#pragma unroll
            for (int k = 0; k < 2; ++k) {
                int i = tid + k * 256;
                int row = i >> 3, q = i & 7;
                *(float4*)&A[row][q * 4] =
                    *(const float4*)&feat[(size_t)(r0 + row) * ND + d0 + q * 4];
            }
#pragma unroll
            for (int k = 0; k < 4; ++k) {
                int i = tid + k * 256;
                int drow = i >> 5, q = i & 31;
                *(float4*)&Bt[drow][q * 4] =
                    *(const float4*)&g_miT[(size_t)(d0 + drow) * NC + q * 4];
            }
            if (tid < 32) ivs[tid] = g_iv[d0 + tid];
            __syncthreads();

#pragma unroll
            for (int u = 0; u < 2; ++u) {
                int dd = cg + u * 16;
                float iv = ivs[dd];
#pragma unroll
                for (int i = 0; i < 4; ++i) {
                    float a = A[rr + 16 * i][dd];
                    xq[i] = fmaf(a * iv, a, xq[i]);
                }
            }

#pragma unroll 8
            for (int dd = 0; dd < 32; ++dd) {
                U2 b0, b1;
                b0.f4 = *(const float4*)&Bt[dd][cg * 4];
                b1.f4 = *(const float4*)&Bt[dd][64 + cg * 4];
#pragma unroll
                for (int i = 0; i < 4; ++i) {
                    float a = A[rr + 16 * i][dd];
                    ull aa;
                    PACK2(aa, a, a);
                    FMA2(acc2[i][0], aa, b0.u[0]);
                    FMA2(acc2[i][1], aa, b0.u[1]);
                    FMA2(acc2[i][2], aa, b1.u[0]);
                    FMA2(acc2[i][3], aa, b1.u[1]);
                }
            }
        }

#pragma unroll
        for (int o = 1; o < 16; o <<= 1) {
#pragma unroll
            for (int i = 0; i < 4; ++i)
                xq[i] += __shfl_xor_sync(0xffffffffu, xq[i], o, 16);
        }

        float cb[8];
        {
            float4 cb0 = *(const float4*)&g_cb[cg * 4];
            float4 cb1 = *(const float4*)&g_cb[64 + cg * 4];
            cb[0] = cb0.x; cb[1] = cb0.y; cb[2] = cb0.z; cb[3] = cb0.w;
            cb[4] = cb1.x; cb[5] = cb1.y; cb[6] = cb1.z; cb[7] = cb1.w;
        }
        const float L2E = 1.4426950408889634f;

#pragma unroll
        for (int i = 0; i < 4; ++i) {
            float hq = -0.5f * xq[i];
            float e[8], m = -3.0e38f;
#pragma unroll
            for (int k = 0; k < 4; ++k) {
                float lo, hi;
                UNPACK2(lo, hi, acc2[i][k]);
                e[k * 2] = lo + hq + cb[k * 2];
                e[k * 2 + 1] = hi + hq + cb[k * 2 + 1];
            }
#pragma unroll
            for (int k = 0; k < 8; ++k) m = fmaxf(m, e[k]);
#pragma unroll
            for (int off = 8; off >= 1; off >>= 1)
                m = fmaxf(m, __shfl_xor_sync(0xffffffffu, m, off, 16));
            float4 o0, o1;
            o0.x = exp2f((e[0] - m) * L2E); o0.y = exp2f((e[1] - m) * L2E);
            o0.z = exp2f((e[2] - m) * L2E); o0.w = exp2f((e[3] - m) * L2E);
            o1.x = exp2f((e[4] - m) * L2E); o1.y = exp2f((e[5] - m) * L2E);
            o1.z = exp2f((e[6] - m) * L2E); o1.w = exp2f((e[7] - m) * L2E);
            size_t row = (size_t)(r0 + rr + 16 * i);
            *(float4*)&g_f[row * NC + cg * 4] = o0;
            *(float4*)&g_f[row * NC + 64 + cg * 4] = o1;
            if (cg == 0) g_mu[row] = m;
        }

        __threadfence();
        __syncthreads();
        if (tid == 0) atomicExch(&g_done[b * NCHUNK + chunk], 1);
        return;
    }

    // ================= recursion consumer (bf16 matvec + packed window) =====
    if (threadIdx.x >= 128) return;

    const int b = blockIdx.x, c = threadIdx.x;
    const int w = c >> 5, lane = c & 31;
    __shared__ __align__(16) unsigned short psb[2][NC];  // alpha as bf16
    __shared__ float shs[4];

    // E row as bf16x2: 64 regs
    unsigned Eb[64];
#pragma unroll
    for (int k = 0; k < 64; ++k) {
        __nv_bfloat162 t2 = __floats2bfloat162_rn(g_E[c * NC + 2 * k],
                                                  g_E[c * NC + 2 * k + 1]);
        Eb[k] = *(unsigned*)&t2;
    }
    const float Dr0 = g_dtab[c];
    // Dp[k] = bf16x2(D[2k+1], D[2k+2]) for dot over new window; D[20]=0
    unsigned Dp[10];
#pragma unroll
    for (int k = 0; k < 10; ++k) {
        float d1 = g_dtab[(2 * k + 1) * NC + c];
        float d2 = (2 * k + 2 < MAXK) ? g_dtab[(2 * k + 2) * NC + c] : 0.0f;
        __nv_bfloat162 t2 = __floats2bfloat162_rn(d1, d2);
        Dp[k] = *(unsigned*)&t2;
    }
    // packed bf16 window: W[k] = (v[2k], v[2k+1]); 10 regs cover v[0..19]
    unsigned W[10];
#pragma unroll
    for (int k = 0; k < 10; ++k) W[k] = 0u;

    const int len = lengths[b];
    const float* fp = g_f + (size_t)b * NT * NC;
    const float* mup = g_mu + b * NT;

    int qready = -1;
#define WAIT_CHUNK(q)                                                        \
    if ((q) > qready) {                                                      \
        const int* fl = &g_done[b * NCHUNK + (q)];                           \
        int d_;                                                              \
        do {                                                                 \
            asm volatile("ld.global.cg.b32 %0, [%1];" : "=r"(d_) : "l"(fl) : "memory"); \
            if (!d_) __nanosleep(64);                                        \
        } while (!d_);                                                       \
        qready = (q);                                                        \
        __threadfence();                                                     \
    }

    WAIT_CHUNK(0);

    float wv = g_winit[c];
    float fr_cur = __ldg(&fp[c]);           // f_0 * rm(=1)
    float al = fr_cur * (wv * Dr0);         // alpha_1 (window empty)
    float sigma = __ldg(&mup[0]);
    int ks = 0;
    float rm = 1.0f;
    int kcur = 0;
    float fA = __ldg(&fp[NC + c]),     muA = __ldg(&mup[1]);
    float fB = __ldg(&fp[2 * NC + c]), muB = __ldg(&mup[2]);

    for (int t = 1;; ++t) {
        const int par = t & 1;

        if (t == len) {
            float s = al;
#pragma unroll
            for (int o = 16; o >= 1; o >>= 1)
                s += __shfl_xor_sync(0xffffffffu, s, o);
            if (lane == 0) shs[w] = s;
            __syncthreads();
            if (c == 0) {
                float st = (shs[0] + shs[1]) + (shs[2] + shs[3]);
                out[b] = sigma + (float)ks * 0.6931471805599453f + logf(st);
            }
            break;
        }

        // minimal pre-barrier chain: publish alpha (bf16), barrier
        {
            __nv_bfloat16 ab = __float2bfloat16(al);
            psb[par][c] = *(unsigned short*)&ab;
        }
        __syncthreads();

        // prefetch row t+2 (wait for its chunk first; nearly always ready)
        int tn = (t + 2 < NT) ? t + 2 : (NT - 1);
        WAIT_CHUNK(tn >> 6);
        float fN = __ldg(&fp[(size_t)tn * NC + c]);
        float muN = __ldg(&mup[tn]);

        // block max of alpha_t from psb (bf16 -> f32 bit space), exponent only
        {
            uint2 q2 = ((const uint2*)&psb[par][0])[lane];
            unsigned v0 = q2.x << 16, v1 = q2.x & 0xffff0000u;
            unsigned v2 = q2.y << 16, v3 = q2.y & 0xffff0000u;
            unsigned m01 = v0 > v1 ? v0 : v1;
            unsigned m23 = v2 > v3 ? v2 : v3;
            unsigned qm = m01 > m23 ? m01 : m23;
            unsigned mm;
            asm("redux.sync.max.u32 %0, %1, 0xffffffff;" : "=r"(mm) : "r"(qm));
            unsigned e = mm >> 23;
            rm = __uint_as_float((254u - e) << 23);     // 2^(127-e)
            kcur = (int)e - 127;
        }

        // packed bf16 window update (shift via byte_perm, scale by fr_cur)
        // then duration dot for NEXT alpha (independent of new wv)
        float dsum;
        {
            unsigned fr2b, pw;
            {
                __nv_bfloat162 tf = __floats2bfloat162_rn(fr_cur, fr_cur);
                fr2b = *(unsigned*)&tf;
                __nv_bfloat162 tw = __floats2bfloat162_rn(wv, wv);
                pw = *(unsigned*)&tw;
            }
            unsigned p0 = __byte_perm(pw, W[0], 0x5410);   // (wv, v0)
            unsigned p9 = __byte_perm(W[8], W[9], 0x5432);
            unsigned p8 = __byte_perm(W[7], W[8], 0x5432);
            unsigned p7 = __byte_perm(W[6], W[7], 0x5432);
            unsigned p6 = __byte_perm(W[5], W[6], 0x5432);
            unsigned p5 = __byte_perm(W[4], W[5], 0x5432);
            unsigned p4 = __byte_perm(W[3], W[4], 0x5432);
            unsigned p3 = __byte_perm(W[2], W[3], 0x5432);
            unsigned p2 = __byte_perm(W[1], W[2], 0x5432);
            unsigned p1 = __byte_perm(W[0], W[1], 0x5432);
            HMUL2BF(W[9], p9, fr2b);
            HMUL2BF(W[8], p8, fr2b);
            HMUL2BF(W[7], p7, fr2b);
            HMUL2BF(W[6], p6, fr2b);
            HMUL2BF(W[5], p5, fr2b);
            HMUL2BF(W[4], p4, fr2b);
            HMUL2BF(W[3], p3, fr2b);
            HMUL2BF(W[2], p2, fr2b);
            HMUL2BF(W[1], p1, fr2b);
            HMUL2BF(W[0], p0, fr2b);
            unsigned h0 = 0u, h1 = 0u;
#pragma unroll
            for (int k = 0; k < 10; k += 2) {
                HFMA2BF(h0, W[k], Dp[k]);
                HFMA2BF(h1, W[k + 1], Dp[k + 1]);
            }
            float f0 = __uint_as_float(h0 << 16) + __uint_as_float(h0 & 0xffff0000u);
            float f1 = __uint_as_float(h1 << 16) + __uint_as_float(h1 & 0xffff0000u);
            dsum = f0 + f1;
        }

        // full-row matvec in bf16: wv = E[c,:].alpha
        {
            const uint4* pb4 = (const uint4*)&psb[par][0];
            unsigned a0 = 0u, a1 = 0u, a2 = 0u, a3 = 0u;
#pragma unroll
            for (int kk = 0; kk < 16; ++kk) {
                uint4 q = pb4[kk];
                HFMA2BF(a0, Eb[4 * kk + 0], q.x);
                HFMA2BF(a1, Eb[4 * kk + 1], q.y);
                HFMA2BF(a2, Eb[4 * kk + 2], q.z);
                HFMA2BF(a3, Eb[4 * kk + 3], q.w);
            }
            float f0 = __uint_as_float(a0 << 16) + __uint_as_float(a0 & 0xffff0000u);
            float f1 = __uint_as_float(a1 << 16) + __uint_as_float(a1 & 0xffff0000u);
            float f2 = __uint_as_float(a2 << 16) + __uint_as_float(a2 & 0xffff0000u);
            float f3 = __uint_as_float(a3 << 16) + __uint_as_float(a3 & 0xffff0000u);
            wv = (f0 + f1) + (f2 + f3);
        }

        // next alpha: 2-op tail after wv
        fr_cur = fA * rm;
        al = fr_cur * fmaf(wv, Dr0, dsum);
        sigma += muA;
        ks += kcur;

        fA = fB; muA = muB; fB = fN; muB = muN;
    }
#undef WAIT_CHUNK
}

extern "C" void kernel_launch(void* const* d_in, const int* in_sizes, int n_in,
                              void* d_out, int out_size) {
    const float* feat    = (const float*)d_in[0];
    const int*   lengths = (const int*)d_in[1];
    const float* means   = (const float*)d_in[2];
    const float* cov     = (const float*)d_in[3];
    const float* trans   = (const float*)d_in[4];
    const float* initlg  = (const float*)d_in[5];
    const float* lograte = (const float*)d_in[6];
    float* out = (float*)d_out;

    prep_misc<<<1, 256>>>(means, cov, initlg, lograte);
    prep_trans<<<1, 1024>>>(trans);
    prep_miT<<<32, 256>>>(means, cov);
    fused_kernel<<<NB + NB * NCHUNK, 256>>>(feat, lengths, out);
}

// round 17
// speedup vs baseline: 1.9646x; 1.1619x over previous
#include <cuda_runtime.h>
#include <cuda_bf16.h>
#include <math.h>
#include <stdint.h>

#define NB 16
#define NT 2048
#define ND 256
#define NC 128
#define MAXK 20
#define WLEN 19      // live window elements
#define CHROWS 64    // emission chunk rows
#define NCHUNK (NT / CHROWS)   // 32

typedef unsigned long long ull;

union U2 { float4 f4; ull u[2]; };

#define FMA2(acc, a, b) asm("fma.rn.f32x2 %0, %1, %2, %0;" : "+l"(acc) : "l"(a), "l"(b))
#define PACK2(d, x, y)  asm("mov.b64 %0, {%1, %2};" : "=l"(d) : "f"(x), "f"(y))
#define UNPACK2(x, y, d) asm("mov.b64 {%0, %1}, %2;" : "=f"(x), "=f"(y) : "l"(d))
#define HFMA2BF(acc, a, b) asm("fma.rn.bf16x2 %0, %1, %2, %0;" : "+r"(acc) : "r"(a), "r"(b))
#define HADD2BF(d, a, b)   asm("add.rn.bf16x2 %0, %1, %2;" : "=r"(d) : "r"(a), "r"(b))

// ---------- device scratch ----------
__device__ float g_E[NC * NC];
__device__ float g_winit[NC];
__device__ float g_dtab[MAXK * NC];
__device__ float g_miT[ND * NC];
__device__ float g_cb[NC];
__device__ float g_iv[ND];
__device__ float g_f[(size_t)NB * NT * NC];
__device__ float g_mu[NB * NT];
__device__ int   g_done[NB * NCHUNK];

// ---------- prep_misc: 1 block x 256 ----------
__global__ void prep_misc(const float* __restrict__ means,
                          const float* __restrict__ cov,
                          const float* __restrict__ initlg,
                          const float* __restrict__ lograte) {
    const int t = threadIdx.x;
    const int lane = t & 31, w = t >> 5;
    __shared__ float red[8];
    __shared__ float s_cst;
    __shared__ float s_iv[ND];

    g_done[t] = 0;
    g_done[t + 256] = 0;

    float cv = cov[t];
    float iv = __fdividef(1.0f, cv);
    g_iv[t] = iv;
    s_iv[t] = iv;
    float ls = __logf(cv);
#pragma unroll
    for (int o = 16; o >= 1; o >>= 1)
        ls += __shfl_xor_sync(0xffffffffu, ls, o);
    if (lane == 0) red[w] = ls;
    __syncthreads();
    if (t == 0) {
        float tot = 0.f;
        for (int i = 0; i < 8; ++i) tot += red[i];
        s_cst = -0.5f * (256.0f * 1.8378770664093453f + tot);
    }
    __syncthreads();
    const float cst = s_cst;

    for (int ci = 0; ci < 16; ++ci) {
        int c = ci * 8 + w;
        float p = 0.f;
#pragma unroll
        for (int k = 0; k < 8; ++k) {
            int d = k * 32 + lane;
            float m = means[c * ND + d];
            p = fmaf(m * m, s_iv[d], p);
        }
#pragma unroll
        for (int o = 16; o >= 1; o >>= 1)
            p += __shfl_xor_sync(0xffffffffu, p, o);
        if (lane == 0) g_cb[c] = cst - 0.5f * p;
    }

    if (t < NC) {
        float il = initlg[t];
        float mx = il;
#pragma unroll
        for (int o = 16; o >= 1; o >>= 1)
            mx = fmaxf(mx, __shfl_xor_sync(0xffffffffu, mx, o));
        if (lane == 0) red[w] = mx;
    }
    __syncthreads();
    if (t < NC) {
        float mx = fmaxf(fmaxf(red[0], red[1]), fmaxf(red[2], red[3]));
        float il = initlg[t];
        float ex = __expf(il - mx);
        float s = ex;
#pragma unroll
        for (int o = 16; o >= 1; o >>= 1)
            s += __shfl_xor_sync(0xffffffffu, s, o);
        if (lane == 0) red[4 + w] = s;
        __syncthreads();
        float tot = (red[4] + red[5]) + (red[6] + red[7]);
        g_winit[t] = __fdividef(ex, tot);

        float r = lograte[t];
        float lam = __expf(r);
        float lg = 0.f;
        for (int l = 1; l <= MAXK; ++l) {
            lg += __logf((float)l);
            g_dtab[(l - 1) * NC + t] = __expf(fmaf((float)l, r, -lam) - lg);
        }
    }
}

// ---------- prep_trans: 1 block x 1024 ----------
__global__ __launch_bounds__(1024) void prep_trans(const float* __restrict__ trans) {
    const int t = threadIdx.x;
    const int j = t & 127;
    const int g = t >> 7;
    __shared__ float gmax[8][NC];
    __shared__ float gsum[8][NC];
    __shared__ float colmax[NC], colinv[NC];

    float v[16];
    float mx = -3.0e38f;
#pragma unroll
    for (int k = 0; k < 16; ++k) {
        int i = g * 16 + k;
        float x = trans[i * NC + j];
        if (i == j) x = -1.0e9f;
        v[k] = x;
        mx = fmaxf(mx, x);
    }
    gmax[g][j] = mx;
    __syncthreads();
    if (t < NC) {
        float m = gmax[0][t];
#pragma unroll
        for (int i = 1; i < 8; ++i) m = fmaxf(m, gmax[i][t]);
        colmax[t] = m;
    }
    __syncthreads();
    float cm = colmax[j];
    float ex[16], s = 0.f;
#pragma unroll
    for (int k = 0; k < 16; ++k) {
        ex[k] = __expf(v[k] - cm);
        s += ex[k];
    }
    gsum[g][j] = s;
    __syncthreads();
    if (t < NC) {
        float ss = 0.f;
#pragma unroll
        for (int i = 0; i < 8; ++i) ss += gsum[i][t];
        colinv[t] = __fdividef(1.0f, ss);
    }
    __syncthreads();
    float inv = colinv[j];
#pragma unroll
    for (int k = 0; k < 16; ++k) {
        int i = g * 16 + k;
        g_E[i * NC + j] = (i == j) ? 0.0f : ex[k] * inv;
    }
}

// ---------- prep_miT: 32 blocks x 256 ----------
__global__ void prep_miT(const float* __restrict__ means,
                         const float* __restrict__ cov) {
    __shared__ float tile[32][33];
    const int t = threadIdx.x;
    const int tc = blockIdx.x & 3, td = blockIdx.x >> 2;
    const int c0 = tc * 32, d0 = td * 32;
    const int r = t >> 5, dl = t & 31;

    float iv = __fdividef(1.0f, cov[d0 + dl]);
#pragma unroll
    for (int k = 0; k < 4; ++k) {
        int rr = r + 8 * k;
        tile[rr][dl] = means[(c0 + rr) * ND + d0 + dl] * iv;
    }
    __syncthreads();
#pragma unroll
    for (int k = 0; k < 4; ++k) {
        int dr = r + 8 * k;
        g_miT[(d0 + dr) * NC + c0 + dl] = tile[dl][dr];
    }
}

// ---------- fused kernel: 16 rec blocks + 512 emission producers ----------
__global__ __launch_bounds__(256) void fused_kernel(const float* __restrict__ feat,
                                                    const int* __restrict__ lengths,
                                                    float* __restrict__ out) {
    if (blockIdx.x >= NB) {
        // ================= emission producer: 64 rows =================
        const int eb = blockIdx.x - NB;
        const int chunk = eb >> 4;
        const int b = eb & 15;
        const int r0 = b * NT + chunk * CHROWS;

        __shared__ float A[CHROWS][40];
        __shared__ float Bt[32][132];
        __shared__ float ivs[32];

        const int tid = threadIdx.x;
        const int cg = tid & 15;
        const int rr = tid >> 4;

        ull acc2[4][4];
#pragma unroll
        for (int i = 0; i < 4; ++i)
#pragma unroll
            for (int k = 0; k < 4; ++k) acc2[i][k] = 0ull;
        float xq[4] = {0.f, 0.f, 0.f, 0.f};

        for (int d0 = 0; d0 < ND; d0 += 32) {
            __syncthreads();
#pragma unroll
            for (int k = 0; k < 2; ++k) {
                int i = tid + k * 256;
                int row = i >> 3, q = i & 7;
                *(float4*)&A[row][q * 4] =
                    *(const float4*)&feat[(size_t)(r0 + row) * ND + d0 + q * 4];
            }
#pragma unroll
            for (int k = 0; k < 4; ++k) {
                int i = tid + k * 256;
                int drow = i >> 5, q = i & 31;
                *(float4*)&Bt[drow][q * 4] =
                    *(const float4*)&g_miT[(size_t)(d0 + drow) * NC + q * 4];
            }
            if (tid < 32) ivs[tid] = g_iv[d0 + tid];
            __syncthreads();

#pragma unroll
            for (int u = 0; u < 2; ++u) {
                int dd = cg + u * 16;
                float iv = ivs[dd];
#pragma unroll
                for (int i = 0; i < 4; ++i) {
                    float a = A[rr + 16 * i][dd];
                    xq[i] = fmaf(a * iv, a, xq[i]);
                }
            }

#pragma unroll 8
            for (int dd = 0; dd < 32; ++dd) {
                U2 b0, b1;
                b0.f4 = *(const float4*)&Bt[dd][cg * 4];
                b1.f4 = *(const float4*)&Bt[dd][64 + cg * 4];
#pragma unroll
                for (int i = 0; i < 4; ++i) {
                    float a = A[rr + 16 * i][dd];
                    ull aa;
                    PACK2(aa, a, a);
                    FMA2(acc2[i][0], aa, b0.u[0]);
                    FMA2(acc2[i][1], aa, b0.u[1]);
                    FMA2(acc2[i][2], aa, b1.u[0]);
                    FMA2(acc2[i][3], aa, b1.u[1]);
                }
            }
        }

#pragma unroll
        for (int o = 1; o < 16; o <<= 1) {
#pragma unroll
            for (int i = 0; i < 4; ++i)
                xq[i] += __shfl_xor_sync(0xffffffffu, xq[i], o, 16);
        }

        float cb[8];
        {
            float4 cb0 = *(const float4*)&g_cb[cg * 4];
            float4 cb1 = *(const float4*)&g_cb[64 + cg * 4];
            cb[0] = cb0.x; cb[1] = cb0.y; cb[2] = cb0.z; cb[3] = cb0.w;
            cb[4] = cb1.x; cb[5] = cb1.y; cb[6] = cb1.z; cb[7] = cb1.w;
        }
        const float L2E = 1.4426950408889634f;

#pragma unroll
        for (int i = 0; i < 4; ++i) {
            float hq = -0.5f * xq[i];
            float e[8], m = -3.0e38f;
#pragma unroll
            for (int k = 0; k < 4; ++k) {
                float lo, hi;
                UNPACK2(lo, hi, acc2[i][k]);
                e[k * 2] = lo + hq + cb[k * 2];
                e[k * 2 + 1] = hi + hq + cb[k * 2 + 1];
            }
#pragma unroll
            for (int k = 0; k < 8; ++k) m = fmaxf(m, e[k]);
#pragma unroll
            for (int off = 8; off >= 1; off >>= 1)
                m = fmaxf(m, __shfl_xor_sync(0xffffffffu, m, off, 16));
            float4 o0, o1;
            o0.x = exp2f((e[0] - m) * L2E); o0.y = exp2f((e[1] - m) * L2E);
            o0.z = exp2f((e[2] - m) * L2E); o0.w = exp2f((e[3] - m) * L2E);
            o1.x = exp2f((e[4] - m) * L2E); o1.y = exp2f((e[5] - m) * L2E);
            o1.z = exp2f((e[6] - m) * L2E); o1.w = exp2f((e[7] - m) * L2E);
            size_t row = (size_t)(r0 + rr + 16 * i);
            *(float4*)&g_f[row * NC + cg * 4] = o0;
            *(float4*)&g_f[row * NC + 64 + cg * 4] = o1;
            if (cg == 0) g_mu[row] = m;
        }

        __threadfence();
        __syncthreads();
        if (tid == 0) atomicExch(&g_done[b * NCHUNK + chunk], 1);
        return;
    }

    // ================= recursion consumer (bf16 matvec, f32 window) ==========
    if (threadIdx.x >= 128) return;

    const int b = blockIdx.x, c = threadIdx.x;
    const int w = c >> 5, lane = c & 31;
    __shared__ __align__(16) unsigned short psb[2][NC];  // alpha as bf16 (truncated)
    __shared__ float shs[4];

    // E row as bf16x2: 64 regs
    unsigned Eb[64];
#pragma unroll
    for (int k = 0; k < 64; ++k) {
        __nv_bfloat162 t2 = __floats2bfloat162_rn(g_E[c * NC + 2 * k],
                                                  g_E[c * NC + 2 * k + 1]);
        Eb[k] = *(unsigned*)&t2;
    }
    const float Dr0 = g_dtab[c];
    float Dr[MAXK];
#pragma unroll
    for (int j = 0; j < MAXK; ++j) Dr[j] = g_dtab[j * NC + c];
    float v[WLEN];
#pragma unroll
    for (int j = 0; j < WLEN; ++j) v[j] = 0.f;

    const int len = lengths[b];
    const float* fp = g_f + (size_t)b * NT * NC;
    const float* mup = g_mu + b * NT;

    int qready = -1;
#define WAIT_CHUNK(q)                                                        \
    if ((q) > qready) {                                                      \
        const int* fl = &g_done[b * NCHUNK + (q)];                           \
        int d_;                                                              \
        do {                                                                 \
            asm volatile("ld.global.cg.b32 %0, [%1];" : "=r"(d_) : "l"(fl) : "memory"); \
            if (!d_) __nanosleep(64);                                        \
        } while (!d_);                                                       \
        qready = (q);                                                        \
        __threadfence();                                                     \
    }

    WAIT_CHUNK(0);

    float wv = g_winit[c];
    float fr_cur = __ldg(&fp[c]);           // f_0 * rm(=1)
    float al = fr_cur * (wv * Dr0);         // alpha_1 (window empty)
    float sigma = __ldg(&mup[0]);
    int ks = 0;
    int kcur = 0;
    float rm = 1.0f;
    float fA = __ldg(&fp[NC + c]),     muA = __ldg(&mup[1]);
    float fB = __ldg(&fp[2 * NC + c]), muB = __ldg(&mup[2]);

    for (int t = 1;; ++t) {
        const int par = t & 1;

        if (t == len) {
            float s = al;
#pragma unroll
            for (int o = 16; o >= 1; o >>= 1)
                s += __shfl_xor_sync(0xffffffffu, s, o);
            if (lane == 0) shs[w] = s;
            __syncthreads();
            if (c == 0) {
                float st = (shs[0] + shs[1]) + (shs[2] + shs[3]);
                out[b] = sigma + (float)ks * 0.6931471805599453f + logf(st);
            }
            break;
        }

        // minimal pre-barrier chain: truncation-pack alpha (1 SHF), STS, barrier
        psb[par][c] = (unsigned short)(__float_as_uint(al) >> 16);
        __syncthreads();

        // prefetch row t+2 (wait for its chunk first; nearly always ready)
        int tn = (t + 2 < NT) ? t + 2 : (NT - 1);
        WAIT_CHUNK(tn >> 6);
        float fN = __ldg(&fp[(size_t)tn * NC + c]);
        float muN = __ldg(&mup[tn]);

        // block max of alpha_t from psb (bf16 -> f32 bit space), exponent only
        {
            uint2 q2 = ((const uint2*)&psb[par][0])[lane];
            unsigned v0 = q2.x << 16, v1 = q2.x & 0xffff0000u;
            unsigned v2 = q2.y << 16, v3 = q2.y & 0xffff0000u;
            unsigned m01 = v0 > v1 ? v0 : v1;
            unsigned m23 = v2 > v3 ? v2 : v3;
            unsigned qm = m01 > m23 ? m01 : m23;
            unsigned mm;
            asm("redux.sync.max.u32 %0, %1, 0xffffffff;" : "=r"(mm) : "r"(qm));
            unsigned e = mm >> 23;
            rm = __uint_as_float((254u - e) << 23);     // 2^(127-e)
            kcur = (int)e - 127;
        }

        // window update with fr_cur; uses old wv (19 live elements)
#pragma unroll
        for (int j = WLEN - 1; j >= 1; --j) v[j] = v[j - 1] * fr_cur;
        v[0] = wv * fr_cur;

        // duration dot for NEXT alpha (independent of new wv)
        float d0 = 0.f, d1 = 0.f, d2 = 0.f, d3 = 0.f;
#pragma unroll
        for (int j = 1; j < MAXK; j += 4) {
            d0 = fmaf(v[j - 1], Dr[j], d0);
            if (j + 1 < MAXK) d1 = fmaf(v[j], Dr[j + 1], d1);
            if (j + 2 < MAXK) d2 = fmaf(v[j + 1], Dr[j + 2], d2);
            if (j + 3 < MAXK) d3 = fmaf(v[j + 2], Dr[j + 3], d3);
        }
        float dsum = (d0 + d1) + (d2 + d3);

        // off-cone precompute: next fr, and fold into gd/hd so the
        // post-matvec tail is a single FMA.
        float fr_nxt = fA * rm;
        float gd = fr_nxt * Dr0;
        float hd = fr_nxt * dsum;

        // full-row matvec in bf16: wv = E[c,:].alpha
        {
            const uint4* pb4 = (const uint4*)&psb[par][0];
            unsigned a0 = 0u, a1 = 0u, a2 = 0u, a3 = 0u;
#pragma unroll
            for (int kk = 0; kk < 16; ++kk) {
                uint4 q = pb4[kk];
                HFMA2BF(a0, Eb[4 * kk + 0], q.x);
                HFMA2BF(a1, Eb[4 * kk + 1], q.y);
                HFMA2BF(a2, Eb[4 * kk + 2], q.z);
                HFMA2BF(a3, Eb[4 * kk + 3], q.w);
            }
            unsigned h01, h23, h;
            HADD2BF(h01, a0, a1);
            HADD2BF(h23, a2, a3);
            HADD2BF(h, h01, h23);
            wv = __uint_as_float(h << 16) + __uint_as_float(h & 0xffff0000u);
        }

        // next alpha: 1-op tail after wv
        al = fmaf(wv, gd, hd);
        fr_cur = fr_nxt;
        sigma += muA;
        ks += kcur;

        fA = fB; muA = muB; fB = fN; muB = muN;
    }
#undef WAIT_CHUNK
}

extern "C" void kernel_launch(void* const* d_in, const int* in_sizes, int n_in,
                              void* d_out, int out_size) {
    const float* feat    = (const float*)d_in[0];
    const int*   lengths = (const int*)d_in[1];
    const float* means   = (const float*)d_in[2];
    const float* cov     = (const float*)d_in[3];
    const float* trans   = (const float*)d_in[4];
    const float* initlg  = (const float*)d_in[5];
    const float* lograte = (const float*)d_in[6];
    float* out = (float*)d_out;

    prep_misc<<<1, 256>>>(means, cov, initlg, lograte);
    prep_trans<<<1, 1024>>>(trans);
    prep_miT<<<32, 256>>>(means, cov);
    fused_kernel<<<NB + NB * NCHUNK, 256>>>(feat, lengths, out);
}